// round 13
// baseline (speedup 1.0000x reference)
#include <cuda_runtime.h>
#include <cuda_bf16.h>
#include <stdint.h>

// ---------------------------------------------------------------------------
// Problem constants
// ---------------------------------------------------------------------------
#define N_ROWS   16384
#define DDIM     17          // DATA_DIM+1
#define DH       64
#define LEN_M    1088
#define M_PRI    65
#define M0       100
#define M1       100
#define PRED_ELEMS (16384UL * 100UL * 100UL)   // 163,840,000

#define W1S_STRIDE 104
#define ZS_STRIDE  72
#define NBLKS      256            // 16384/64 n-blocks
#define NTILES     (M0 * NBLKS)   // 25600
#define GRID_MAIN  592            // 148 SMs x 4 resident CTAs

// Scratch (allocation-free: __device__ globals)
__device__ float g_W0T[M0 * LEN_M];            // [m][d*64+h] contiguous per m
__device__ float g_W1P[M_PRI * W1S_STRIDE];    // [d][c] padded, tf32-pre-rounded (d>0)
__device__ float g_XT [DDIM * N_ROWS];         // [d][n] transposed x

// ---------------------------------------------------------------------------
// Threefry-2x32 (JAX convention, 20 rounds)
// ---------------------------------------------------------------------------
__host__ __device__ inline uint32_t rotl32(uint32_t x, int r) {
    return (x << r) | (x >> (32 - r));
}

__host__ __device__ inline void threefry2x32(uint32_t k0, uint32_t k1,
                                             uint32_t x0, uint32_t x1,
                                             uint32_t* o0, uint32_t* o1) {
    uint32_t ks0 = k0, ks1 = k1, ks2 = 0x1BD11BDAu ^ k0 ^ k1;
    x0 += ks0; x1 += ks1;
#define TF_ROUND(r) { x0 += x1; x1 = rotl32(x1, r); x1 ^= x0; }
    TF_ROUND(13) TF_ROUND(15) TF_ROUND(26) TF_ROUND(6)
    x0 += ks1; x1 += ks2 + 1u;
    TF_ROUND(17) TF_ROUND(29) TF_ROUND(16) TF_ROUND(24)
    x0 += ks2; x1 += ks0 + 2u;
    TF_ROUND(13) TF_ROUND(15) TF_ROUND(26) TF_ROUND(6)
    x0 += ks0; x1 += ks1 + 3u;
    TF_ROUND(17) TF_ROUND(29) TF_ROUND(16) TF_ROUND(24)
    x0 += ks1; x1 += ks2 + 4u;
    TF_ROUND(13) TF_ROUND(15) TF_ROUND(26) TF_ROUND(6)
    x0 += ks2; x1 += ks0 + 5u;
#undef TF_ROUND
    *o0 = x0; *o1 = x1;
}

__device__ inline uint32_t random_bits_partitionable(uint32_t k0, uint32_t k1,
                                                     uint32_t i) {
    uint32_t o0, o1;
    threefry2x32(k0, k1, 0u, i, &o0, &o1);
    return o0 ^ o1;
}

// JAX normal: bits -> uniform in [-0.99999994, 1) -> sqrt(2)*erfinv(u)
__device__ inline float bits_to_normal(uint32_t bits) {
    float f = __uint_as_float((bits >> 9) | 0x3f800000u) - 1.0f;  // [0,1)
    const float lo = -0.99999994f;
    float u = fmaxf(lo, __fadd_rn(__fmul_rn(f, 2.0f), lo));
    return 1.41421356f * erfinvf(u);
}

// round-to-nearest tf32
__device__ inline float tf32_rna(float x) {
    uint32_t o;
    asm("cvt.rna.tf32.f32 %0, %1;" : "=r"(o) : "f"(x));
    return __uint_as_float(o);
}

// ---------------------------------------------------------------------------
// Prep kernels
// ---------------------------------------------------------------------------
__global__ void gen_w0_kernel(const float* __restrict__ ms_vs,
                              uint32_t k0, uint32_t k1) {
    int i = blockIdx.x * blockDim.x + threadIdx.x;   // flat idx in (1088,100)
    if (i >= LEN_M * M0) return;
    uint32_t bits = random_bits_partitionable(k0, k1, (uint32_t)i);
    int r = i / M0;            // d*64 + h
    int c = i % M0;            // m
    float mean = ms_vs[r];
    float var  = fabsf(ms_vs[LEN_M + M_PRI + r]) + 1e-6f;
    float val  = mean + bits_to_normal(bits) * sqrtf(var);
    g_W0T[c * LEN_M + r] = val;
}

// fills padded, pre-rounded W1P: row 0 exact (bias), rows 1..64 tf32-rna, pad=0
__global__ void gen_w1_kernel(const float* __restrict__ ms_vs,
                              uint32_t k0, uint32_t k1) {
    int i = blockIdx.x * blockDim.x + threadIdx.x;   // over 65*104
    if (i >= M_PRI * W1S_STRIDE) return;
    int r = i / W1S_STRIDE;
    int c = i - r * W1S_STRIDE;
    float v = 0.0f;
    if (c < M1) {
        uint32_t bits = random_bits_partitionable(k0, k1, (uint32_t)(r * M1 + c));
        float mean = ms_vs[LEN_M + r];
        float var  = fabsf(ms_vs[2 * LEN_M + M_PRI + r]) + 1e-6f;
        v = mean + bits_to_normal(bits) * sqrtf(var);
        if (r > 0) v = tf32_rna(v);
    }
    g_W1P[i] = v;
}

// transpose x -> g_XT[d][n] (writes coalesced)
__global__ void transpose_x_kernel(const float* __restrict__ x) {
    int i = blockIdx.x * blockDim.x + threadIdx.x;   // over 17*16384, d-major
    if (i >= DDIM * N_ROWS) return;
    int d = i / N_ROWS;
    int n = i - d * N_ROWS;
    g_XT[i] = x[n * DDIM + d];
}

__global__ void tail_kernel(const float* __restrict__ ms_vs, float* __restrict__ out) {
    int i = blockIdx.x * blockDim.x + threadIdx.x;
    size_t P = PRED_ELEMS;
    if (i < LEN_M) {
        out[P + i]         = ms_vs[i];
        out[P + LEN_M + i] = fabsf(ms_vs[LEN_M + M_PRI + i]) + 1e-6f;
    }
    if (i < M_PRI) {
        out[P + 2 * LEN_M + i]         = ms_vs[LEN_M + i];
        out[P + 2 * LEN_M + M_PRI + i] = fabsf(ms_vs[2 * LEN_M + M_PRI + i]) + 1e-6f;
    }
}

// ---------------------------------------------------------------------------
// Phase-2 MMA helper (identical math to the 332us kernel)
// ---------------------------------------------------------------------------
template<int NT>
__device__ __forceinline__ void phase2_mma(const float* __restrict__ zs,
                                           const float* __restrict__ w1s,
                                           float* __restrict__ out,
                                           int n0, int m, int lane, int rg, int cb0) {
    const int tig = lane & 3;    // thread-in-group
    const int grp = lane >> 2;   // group id (0..7)

    float acc[NT][4];
    // accumulator init = bias row (exact fp32)
#pragma unroll
    for (int tc = 0; tc < NT; tc++) {
        int cc = cb0 + 8 * tc + 2 * tig;
        float b0v = w1s[cc];
        float b1v = w1s[cc + 1];
        acc[tc][0] = b0v; acc[tc][1] = b1v;
        acc[tc][2] = b0v; acc[tc][3] = b1v;
    }

    const int arow = rg * 16 + grp;
    const float* za = zs + tig * ZS_STRIDE + arow;
    const float* wb = w1s + (1 + tig) * W1S_STRIDE + cb0 + grp;

#pragma unroll
    for (int kt = 0; kt < 8; kt++) {
        const int zk = kt * 8 * ZS_STRIDE;
        uint32_t a0 = __float_as_uint(za[zk]);
        uint32_t a1 = __float_as_uint(za[zk + 8]);
        uint32_t a2 = __float_as_uint(za[zk + 4 * ZS_STRIDE]);
        uint32_t a3 = __float_as_uint(za[zk + 4 * ZS_STRIDE + 8]);
        const int wk = kt * 8 * W1S_STRIDE;
#pragma unroll
        for (int tc = 0; tc < NT; tc++) {
            uint32_t b0 = __float_as_uint(wb[wk + 8 * tc]);
            uint32_t b1 = __float_as_uint(wb[wk + 4 * W1S_STRIDE + 8 * tc]);
            asm volatile(
                "mma.sync.aligned.m16n8k8.row.col.f32.tf32.tf32.f32 "
                "{%0,%1,%2,%3}, {%4,%5,%6,%7}, {%8,%9}, {%0,%1,%2,%3};"
                : "+f"(acc[tc][0]), "+f"(acc[tc][1]),
                  "+f"(acc[tc][2]), "+f"(acc[tc][3])
                : "r"(a0), "r"(a1), "r"(a2), "r"(a3), "r"(b0), "r"(b1));
        }
    }

    // epilogue: out[n*10000 + m*100 + c], 32-bit indexing
    uint32_t base0 = (uint32_t)(n0 + rg * 16 + grp) * 10000u + (uint32_t)m * 100u;
    uint32_t base1 = base0 + 80000u;   // +8 rows
#pragma unroll
    for (int tc = 0; tc < NT; tc++) {
        int cc = cb0 + 8 * tc + 2 * tig;
        if (cc < M1) {   // cc even; cc<100 implies cc+1<=99
            *(float2*)&out[base0 + cc] = make_float2(acc[tc][0], acc[tc][1]);
            *(float2*)&out[base1 + cc] = make_float2(acc[tc][2], acc[tc][3]);
        }
    }
}

// ---------------------------------------------------------------------------
// Persistent, software-pipelined main kernel.
// Chunked mapping: CTA owns a contiguous tile range (m changes <=1x per CTA).
// Loop: [prefetch xs(w+1)] phase1(w) | BAR | commit xs(w+1), restage w0 on
// m-boundary, phase2(w) | BAR
// ---------------------------------------------------------------------------
__global__ __launch_bounds__(256, 4)
void main_kernel(float* __restrict__ out) {
    extern __shared__ float sm[];
    float* xs  = sm;                        // [17][64]    1088  (transposed x tile)
    float* w0s = xs + 1088;                 // [17][64]    1088
    float* zs  = w0s + 1088;                // [64][72]    4608
    float* w1s = zs + 64 * ZS_STRIDE;       // [65][104]   6760
    // total 13544 floats = 54176 B -> 4 CTAs/SM

    const int t    = threadIdx.x;
    const int lane = t & 31;
    const int warp = t >> 5;
    const int rg   = warp & 3;
    const int cg   = warp >> 2;
    const int tn   = t & 15, th = t >> 4;
    const int nb   = tn * 4, hb = th * 4;
    // xs prefetch decode for float4 index t (all threads) and t+256 (t<16)
    const int pd0 = t >> 4, pq0 = t & 15;   // row, quad for idx t

    // Balanced contiguous chunks: first 144 CTAs get 44 tiles, rest 43.
    const int extra = NTILES - 43 * GRID_MAIN;   // 144
    const int bid = blockIdx.x;
    int wstart, cnt;
    if (bid < extra) { cnt = 44; wstart = bid * 44; }
    else             { cnt = 43; wstart = extra * 44 + (bid - extra) * 43; }
    const int wend = wstart + cnt;

    // --- prologue: stage w1 (once), w0(m0), xs(first tile)
    {
        const float4* w1g = (const float4*)g_W1P;
        float4* w1d = (float4*)w1s;
#pragma unroll 1
        for (int i = t; i < (M_PRI * W1S_STRIDE) / 4; i += 256) w1d[i] = w1g[i];

        const int m0  = wstart >> 8;
        const int nn0 = (wstart & 255) * 64;
        const float4* w0g = (const float4*)(g_W0T + (size_t)m0 * LEN_M);
        float4* w0d = (float4*)w0s;
        float4* xsd = (float4*)xs;
#pragma unroll 1
        for (int i = t; i < 272; i += 256) {
            int d = i >> 4, q = i & 15;
            xsd[i] = *(const float4*)(g_XT + d * N_ROWS + nn0 + q * 4);
            w0d[i] = w0g[i];
        }
    }
    __syncthreads();

    // --- pipelined persistent loop
#pragma unroll 1
    for (int w = wstart; w < wend; w++) {
        const int m  = w >> 8;
        const int n0 = (w & 255) * 64;
        const int wn = w + 1;
        const bool have_next = (wn < wend);

        // prefetch next xs tile into registers (overlaps phase-1 compute)
        float4 px0, px1;
        if (have_next) {
            const int nn0 = (wn & 255) * 64;
            px0 = *(const float4*)(g_XT + pd0 * N_ROWS + nn0 + pq0 * 4);
            if (t < 16)
                px1 = *(const float4*)(g_XT + 16 * N_ROWS + nn0 + t * 4);
        }

        // --- phase 1: thread computes 4n x 4h block of Z (fma pipe)
        {
            float acc[4][4];
#pragma unroll
            for (int i = 0; i < 4; i++)
#pragma unroll
                for (int j = 0; j < 4; j++) acc[i][j] = 0.0f;

#pragma unroll
            for (int d = 0; d < DDIM; d++) {
                float4 w4 = *(const float4*)&w0s[d * 64 + hb];
                float4 x4 = *(const float4*)&xs [d * 64 + nb];
                float wv[4] = {w4.x, w4.y, w4.z, w4.w};
                float xv[4] = {x4.x, x4.y, x4.z, x4.w};
#pragma unroll
                for (int i = 0; i < 4; i++)
#pragma unroll
                    for (int j = 0; j < 4; j++) acc[i][j] += xv[i] * wv[j];
            }
#pragma unroll
            for (int j = 0; j < 4; j++) {
                float4 v;
                v.x = tf32_rna(fmaxf(acc[0][j], 0.0f));
                v.y = tf32_rna(fmaxf(acc[1][j], 0.0f));
                v.z = tf32_rna(fmaxf(acc[2][j], 0.0f));
                v.w = tf32_rna(fmaxf(acc[3][j], 0.0f));
                *(float4*)&zs[(hb + j) * ZS_STRIDE + nb] = v;
            }
        }
        __syncthreads();   // zs ready; phase-1 reads of xs/w0s done

        // --- commit prefetched xs; restage w0 only on m-boundary (rare)
        if (have_next) {
            ((float4*)xs)[t] = px0;
            if (t < 16) ((float4*)xs)[t + 256] = px1;
            const int nm = wn >> 8;
            if (nm != m) {
                const float4* w0g = (const float4*)(g_W0T + (size_t)nm * LEN_M);
                float4* w0d = (float4*)w0s;
#pragma unroll 1
                for (int i = t; i < 272; i += 256) w0d[i] = w0g[i];
            }
        }

        // --- phase 2: tensor pipe (reads zs, w1s only — no conflict with xs/w0s stores)
        if (cg == 0) phase2_mma<7>(zs, w1s, out, n0, m, lane, rg, 0);
        else         phase2_mma<6>(zs, w1s, out, n0, m, lane, rg, 56);

        __syncthreads();   // phase-2 zs reads done; xs/w0s stores visible
    }
}

// ---------------------------------------------------------------------------
// Launch
// ---------------------------------------------------------------------------
extern "C" void kernel_launch(void* const* d_in, const int* in_sizes, int n_in,
                              void* d_out, int out_size) {
    const float* x     = (const float*)d_in[0];
    const float* ms_vs = (const float*)d_in[1];
    float* out = (float*)d_out;

    // Partitionable threefry split of key(42) = (0, 42)
    uint32_t k0a, k0b, k1a, k1b;
    threefry2x32(0u, 42u, 0u, 0u, &k0a, &k0b);   // child 0 (eps0)
    threefry2x32(0u, 42u, 0u, 1u, &k1a, &k1b);   // child 1 (eps1)

    gen_w0_kernel<<<(LEN_M * M0 + 255) / 256, 256>>>(ms_vs, k0a, k0b);
    gen_w1_kernel<<<(M_PRI * W1S_STRIDE + 255) / 256, 256>>>(ms_vs, k1a, k1b);
    transpose_x_kernel<<<(DDIM * N_ROWS + 255) / 256, 256>>>(x);
    tail_kernel<<<(LEN_M + 255) / 256, 256>>>(ms_vs, out);

    const int smem_bytes = (1088 + 1088 + 64 * ZS_STRIDE + M_PRI * W1S_STRIDE) * 4;
    cudaFuncSetAttribute(main_kernel, cudaFuncAttributeMaxDynamicSharedMemorySize, smem_bytes);
    main_kernel<<<GRID_MAIN, 256, smem_bytes>>>(out);
}

// round 14
// speedup vs baseline: 1.5226x; 1.5226x over previous
#include <cuda_runtime.h>
#include <cuda_bf16.h>
#include <stdint.h>

// ---------------------------------------------------------------------------
// Problem constants
// ---------------------------------------------------------------------------
#define N_ROWS   16384
#define DDIM     17          // DATA_DIM+1
#define DH       64
#define LEN_M    1088
#define M_PRI    65
#define M0       100
#define M1       100
#define PRED_ELEMS (16384UL * 100UL * 100UL)   // 163,840,000

#define W1S_STRIDE 104
#define ZS_STRIDE  72
#define NBLKS      256            // 16384/64 n-blocks
#define NTILES     (M0 * NBLKS)   // 25600
#define GRID_MAIN  592            // 148 SMs x 4 resident CTAs

// Scratch (allocation-free: __device__ globals)
__device__ float g_W0T[M0 * LEN_M];            // [m][d*64+h] contiguous per m
__device__ float g_W1P[M_PRI * W1S_STRIDE];    // [d][c] padded, tf32-pre-rounded (d>0)
__device__ float g_XT [DDIM * N_ROWS];         // [d][n] transposed x

// ---------------------------------------------------------------------------
// Threefry-2x32 (JAX convention, 20 rounds)
// ---------------------------------------------------------------------------
__host__ __device__ inline uint32_t rotl32(uint32_t x, int r) {
    return (x << r) | (x >> (32 - r));
}

__host__ __device__ inline void threefry2x32(uint32_t k0, uint32_t k1,
                                             uint32_t x0, uint32_t x1,
                                             uint32_t* o0, uint32_t* o1) {
    uint32_t ks0 = k0, ks1 = k1, ks2 = 0x1BD11BDAu ^ k0 ^ k1;
    x0 += ks0; x1 += ks1;
#define TF_ROUND(r) { x0 += x1; x1 = rotl32(x1, r); x1 ^= x0; }
    TF_ROUND(13) TF_ROUND(15) TF_ROUND(26) TF_ROUND(6)
    x0 += ks1; x1 += ks2 + 1u;
    TF_ROUND(17) TF_ROUND(29) TF_ROUND(16) TF_ROUND(24)
    x0 += ks2; x1 += ks0 + 2u;
    TF_ROUND(13) TF_ROUND(15) TF_ROUND(26) TF_ROUND(6)
    x0 += ks0; x1 += ks1 + 3u;
    TF_ROUND(17) TF_ROUND(29) TF_ROUND(16) TF_ROUND(24)
    x0 += ks1; x1 += ks2 + 4u;
    TF_ROUND(13) TF_ROUND(15) TF_ROUND(26) TF_ROUND(6)
    x0 += ks2; x1 += ks0 + 5u;
#undef TF_ROUND
    *o0 = x0; *o1 = x1;
}

__device__ inline uint32_t random_bits_partitionable(uint32_t k0, uint32_t k1,
                                                     uint32_t i) {
    uint32_t o0, o1;
    threefry2x32(k0, k1, 0u, i, &o0, &o1);
    return o0 ^ o1;
}

// JAX normal: bits -> uniform in [-0.99999994, 1) -> sqrt(2)*erfinv(u)
__device__ inline float bits_to_normal(uint32_t bits) {
    float f = __uint_as_float((bits >> 9) | 0x3f800000u) - 1.0f;  // [0,1)
    const float lo = -0.99999994f;
    float u = fmaxf(lo, __fadd_rn(__fmul_rn(f, 2.0f), lo));
    return 1.41421356f * erfinvf(u);
}

// round-to-nearest tf32
__device__ inline float tf32_rna(float x) {
    uint32_t o;
    asm("cvt.rna.tf32.f32 %0, %1;" : "=r"(o) : "f"(x));
    return __uint_as_float(o);
}

// 16-byte async copy global -> shared (no destination registers)
__device__ __forceinline__ void cp_async16(uint32_t smem_addr, const void* gptr) {
    asm volatile("cp.async.ca.shared.global [%0], [%1], 16;"
                 :: "r"(smem_addr), "l"(gptr));
}

// ---------------------------------------------------------------------------
// Prep kernels
// ---------------------------------------------------------------------------
__global__ void gen_w0_kernel(const float* __restrict__ ms_vs,
                              uint32_t k0, uint32_t k1) {
    int i = blockIdx.x * blockDim.x + threadIdx.x;   // flat idx in (1088,100)
    if (i >= LEN_M * M0) return;
    uint32_t bits = random_bits_partitionable(k0, k1, (uint32_t)i);
    int r = i / M0;            // d*64 + h
    int c = i % M0;            // m
    float mean = ms_vs[r];
    float var  = fabsf(ms_vs[LEN_M + M_PRI + r]) + 1e-6f;
    float val  = mean + bits_to_normal(bits) * sqrtf(var);
    g_W0T[c * LEN_M + r] = val;
}

// fills padded, pre-rounded W1P: row 0 exact (bias), rows 1..64 tf32-rna, pad=0
__global__ void gen_w1_kernel(const float* __restrict__ ms_vs,
                              uint32_t k0, uint32_t k1) {
    int i = blockIdx.x * blockDim.x + threadIdx.x;   // over 65*104
    if (i >= M_PRI * W1S_STRIDE) return;
    int r = i / W1S_STRIDE;
    int c = i - r * W1S_STRIDE;
    float v = 0.0f;
    if (c < M1) {
        uint32_t bits = random_bits_partitionable(k0, k1, (uint32_t)(r * M1 + c));
        float mean = ms_vs[LEN_M + r];
        float var  = fabsf(ms_vs[2 * LEN_M + M_PRI + r]) + 1e-6f;
        v = mean + bits_to_normal(bits) * sqrtf(var);
        if (r > 0) v = tf32_rna(v);
    }
    g_W1P[i] = v;
}

// transpose x -> g_XT[d][n] (writes coalesced)
__global__ void transpose_x_kernel(const float* __restrict__ x) {
    int i = blockIdx.x * blockDim.x + threadIdx.x;   // over 17*16384, d-major
    if (i >= DDIM * N_ROWS) return;
    int d = i / N_ROWS;
    int n = i - d * N_ROWS;
    g_XT[i] = x[n * DDIM + d];
}

__global__ void tail_kernel(const float* __restrict__ ms_vs, float* __restrict__ out) {
    int i = blockIdx.x * blockDim.x + threadIdx.x;
    size_t P = PRED_ELEMS;
    if (i < LEN_M) {
        out[P + i]         = ms_vs[i];
        out[P + LEN_M + i] = fabsf(ms_vs[LEN_M + M_PRI + i]) + 1e-6f;
    }
    if (i < M_PRI) {
        out[P + 2 * LEN_M + i]         = ms_vs[LEN_M + i];
        out[P + 2 * LEN_M + M_PRI + i] = fabsf(ms_vs[2 * LEN_M + M_PRI + i]) + 1e-6f;
    }
}

// ---------------------------------------------------------------------------
// Phase-2 MMA helper (identical math to the 332us kernel)
// ---------------------------------------------------------------------------
template<int NT>
__device__ __forceinline__ void phase2_mma(const float* __restrict__ zs,
                                           const float* __restrict__ w1s,
                                           float* __restrict__ out,
                                           int n0, int m, int lane, int rg, int cb0) {
    const int tig = lane & 3;    // thread-in-group
    const int grp = lane >> 2;   // group id (0..7)

    float acc[NT][4];
    // accumulator init = bias row (exact fp32)
#pragma unroll
    for (int tc = 0; tc < NT; tc++) {
        int cc = cb0 + 8 * tc + 2 * tig;
        float b0v = w1s[cc];
        float b1v = w1s[cc + 1];
        acc[tc][0] = b0v; acc[tc][1] = b1v;
        acc[tc][2] = b0v; acc[tc][3] = b1v;
    }

    const int arow = rg * 16 + grp;
    const float* za = zs + tig * ZS_STRIDE + arow;
    const float* wb = w1s + (1 + tig) * W1S_STRIDE + cb0 + grp;

#pragma unroll
    for (int kt = 0; kt < 8; kt++) {
        const int zk = kt * 8 * ZS_STRIDE;
        uint32_t a0 = __float_as_uint(za[zk]);
        uint32_t a1 = __float_as_uint(za[zk + 8]);
        uint32_t a2 = __float_as_uint(za[zk + 4 * ZS_STRIDE]);
        uint32_t a3 = __float_as_uint(za[zk + 4 * ZS_STRIDE + 8]);
        const int wk = kt * 8 * W1S_STRIDE;
#pragma unroll
        for (int tc = 0; tc < NT; tc++) {
            uint32_t b0 = __float_as_uint(wb[wk + 8 * tc]);
            uint32_t b1 = __float_as_uint(wb[wk + 4 * W1S_STRIDE + 8 * tc]);
            asm volatile(
                "mma.sync.aligned.m16n8k8.row.col.f32.tf32.tf32.f32 "
                "{%0,%1,%2,%3}, {%4,%5,%6,%7}, {%8,%9}, {%0,%1,%2,%3};"
                : "+f"(acc[tc][0]), "+f"(acc[tc][1]),
                  "+f"(acc[tc][2]), "+f"(acc[tc][3])
                : "r"(a0), "r"(a1), "r"(a2), "r"(a3), "r"(b0), "r"(b1));
        }
    }

    // epilogue: out[n*10000 + m*100 + c], 32-bit indexing
    uint32_t base0 = (uint32_t)(n0 + rg * 16 + grp) * 10000u + (uint32_t)m * 100u;
    uint32_t base1 = base0 + 80000u;   // +8 rows
#pragma unroll
    for (int tc = 0; tc < NT; tc++) {
        int cc = cb0 + 8 * tc + 2 * tig;
        if (cc < M1) {   // cc even; cc<100 implies cc+1<=99
            *(float2*)&out[base0 + cc] = make_float2(acc[tc][0], acc[tc][1]);
            *(float2*)&out[base1 + cc] = make_float2(acc[tc][2], acc[tc][3]);
        }
    }
}

// ---------------------------------------------------------------------------
// Persistent main kernel (R12 mapping: w += GRID_MAIN, all CTAs in lockstep m).
// Staging of the NEXT tile's xs/w0 happens via cp.async in the phase-2 slot:
//   phase1(w) | BAR | cp.async stage(w+G), phase2(w), wait | BAR
// ---------------------------------------------------------------------------
__global__ __launch_bounds__(256, 4)
void main_kernel(float* __restrict__ out) {
    extern __shared__ float sm[];
    float* xs  = sm;                        // [17][64]    1088  (transposed x tile)
    float* w0s = xs + 1088;                 // [17][64]    1088
    float* zs  = w0s + 1088;                // [64][72]    4608
    float* w1s = zs + 64 * ZS_STRIDE;       // [65][104]   6760
    // total 13544 floats = 54176 B -> 4 CTAs/SM

    const int t    = threadIdx.x;
    const int lane = t & 31;
    const int warp = t >> 5;
    const int rg   = warp & 3;
    const int cg   = warp >> 2;
    const int tn   = t & 15, th = t >> 4;
    const int nb   = tn * 4, hb = th * 4;

    const uint32_t xs_s  = (uint32_t)__cvta_generic_to_shared(xs);
    const uint32_t w0s_s = (uint32_t)__cvta_generic_to_shared(w0s);

    // --- stage W1 once per CTA
    {
        const float4* w1g = (const float4*)g_W1P;
        float4* w1d = (float4*)w1s;
#pragma unroll 1
        for (int i = t; i < (M_PRI * W1S_STRIDE) / 4; i += 256) w1d[i] = w1g[i];
    }

    // --- stage first tile synchronously
    {
        const int w0i = blockIdx.x;
        if (w0i < NTILES) {
            const int m0  = w0i >> 8;
            const int nn0 = (w0i & 255) * 64;
            const float4* w0g = (const float4*)(g_W0T + (size_t)m0 * LEN_M);
            float4* w0d = (float4*)w0s;
            float4* xsd = (float4*)xs;
#pragma unroll 1
            for (int i = t; i < 272; i += 256) {
                int d = i >> 4, q = i & 15;
                xsd[i] = *(const float4*)(g_XT + d * N_ROWS + nn0 + q * 4);
                w0d[i] = w0g[i];
            }
        }
    }
    __syncthreads();

    // --- persistent loop (same mapping as the 332us kernel)
#pragma unroll 1
    for (int w = blockIdx.x; w < NTILES; w += GRID_MAIN) {
        const int m  = w >> 8;
        const int n0 = (w & 255) * 64;

        // --- phase 1: thread computes 4n x 4h block of Z (fma pipe)
        {
            float acc[4][4];
#pragma unroll
            for (int i = 0; i < 4; i++)
#pragma unroll
                for (int j = 0; j < 4; j++) acc[i][j] = 0.0f;

#pragma unroll
            for (int d = 0; d < DDIM; d++) {
                float4 w4 = *(const float4*)&w0s[d * 64 + hb];
                float4 x4 = *(const float4*)&xs [d * 64 + nb];
                float wv[4] = {w4.x, w4.y, w4.z, w4.w};
                float xv[4] = {x4.x, x4.y, x4.z, x4.w};
#pragma unroll
                for (int i = 0; i < 4; i++)
#pragma unroll
                    for (int j = 0; j < 4; j++) acc[i][j] += xv[i] * wv[j];
            }
#pragma unroll
            for (int j = 0; j < 4; j++) {
                float4 v;
                v.x = tf32_rna(fmaxf(acc[0][j], 0.0f));
                v.y = tf32_rna(fmaxf(acc[1][j], 0.0f));
                v.z = tf32_rna(fmaxf(acc[2][j], 0.0f));
                v.w = tf32_rna(fmaxf(acc[3][j], 0.0f));
                *(float4*)&zs[(hb + j) * ZS_STRIDE + nb] = v;
            }
        }
        __syncthreads();   // zs ready; phase-1 reads of xs/w0s done

        // --- async-stage NEXT tile's xs/w0 into smem (overlaps phase 2)
        const int wn = w + GRID_MAIN;
        if (wn < NTILES) {
            const int nm  = wn >> 8;
            const int nn0 = (wn & 255) * 64;
            const float* w0g = g_W0T + (size_t)nm * LEN_M;
#pragma unroll 1
            for (int i = t; i < 272; i += 256) {
                int d = i >> 4, q = i & 15;
                cp_async16(xs_s  + i * 16, g_XT + d * N_ROWS + nn0 + q * 4);
                cp_async16(w0s_s + i * 16, w0g + i * 4);
            }
        }
        asm volatile("cp.async.commit_group;" ::: "memory");

        // --- phase 2: tensor pipe (reads zs/w1s only — disjoint from xs/w0s)
        if (cg == 0) phase2_mma<7>(zs, w1s, out, n0, m, lane, rg, 0);
        else         phase2_mma<6>(zs, w1s, out, n0, m, lane, rg, 56);

        asm volatile("cp.async.wait_group 0;" ::: "memory");
        __syncthreads();   // staged xs/w0 visible; phase-2 zs reads done
    }
}

// ---------------------------------------------------------------------------
// Launch
// ---------------------------------------------------------------------------
extern "C" void kernel_launch(void* const* d_in, const int* in_sizes, int n_in,
                              void* d_out, int out_size) {
    const float* x     = (const float*)d_in[0];
    const float* ms_vs = (const float*)d_in[1];
    float* out = (float*)d_out;

    // Partitionable threefry split of key(42) = (0, 42)
    uint32_t k0a, k0b, k1a, k1b;
    threefry2x32(0u, 42u, 0u, 0u, &k0a, &k0b);   // child 0 (eps0)
    threefry2x32(0u, 42u, 0u, 1u, &k1a, &k1b);   // child 1 (eps1)

    gen_w0_kernel<<<(LEN_M * M0 + 255) / 256, 256>>>(ms_vs, k0a, k0b);
    gen_w1_kernel<<<(M_PRI * W1S_STRIDE + 255) / 256, 256>>>(ms_vs, k1a, k1b);
    transpose_x_kernel<<<(DDIM * N_ROWS + 255) / 256, 256>>>(x);
    tail_kernel<<<(LEN_M + 255) / 256, 256>>>(ms_vs, out);

    const int smem_bytes = (1088 + 1088 + 64 * ZS_STRIDE + M_PRI * W1S_STRIDE) * 4;
    cudaFuncSetAttribute(main_kernel, cudaFuncAttributeMaxDynamicSharedMemorySize, smem_bytes);
    main_kernel<<<GRID_MAIN, 256, smem_bytes>>>(out);
}